// round 14
// baseline (speedup 1.0000x reference)
#include <cuda_runtime.h>
#include <cstdint>

// Problem constants
#define Bn  128
#define Tn  512
#define In  128
#define Hn  512
#define NCn 100
#define Vn  101   // NC+1 token values

// Recurrent kernel tiling: 128 blocks = 8 row-tiles (16 batches) x 16 col-tiles (32 h)
#define GRID_R 128
#define THR_R  512          // 16 warps, each owns a 32-k slice; weight-stationary regs
#define ASD_ULL (16*16*32)          // dup-A: [warp][16 r][32 kk] ull  (64KB)
#define PS_FLOATS (16*16*64)        // 16 partial slots (64KB)
#define SMEM_R_BYTES (ASD_ULL*8 + PS_FLOATS*4)   // 131072 B

typedef unsigned long long ull;

// packed dual-fp32 ops (sm_100+)
#define FMA2(accv, av, bv) \
    asm("fma.rn.f32x2 %0, %1, %2, %0;" : "+l"(accv) : "l"(av), "l"(bv))
#define ADD2(accv, bv) \
    asm("add.rn.f32x2 %0, %0, %1;" : "+l"(accv) : "l"(bv))
#define PACK_DUP(dst, s) \
    asm("mov.b64 %0, {%1, %1};" : "=l"(dst) : "f"(s))

// ---------------- device-global scratch ----------------
__device__ float d_gtab[Vn * 4 * Hn];     // [tok][gate f,i,o,sig(c)][h]
__device__ float d_Wpack[Hn * 2 * Hn];    // [k][2h+g] g=0:f g=1:i
__device__ float d_CT[2][Hn * Bn];        // cell state [h][b] (Cold prefetch + finals)
__device__ float d_CB[2][Bn * Hn];        // cell state [b][h] (row-major, for A staging)
__device__ float d_Hf[Bn * Hn];
__device__ unsigned int d_barArr[8 * 32]; // per-row-group monotonic counters

__device__ __forceinline__ float sigf(float x) { return 1.0f / (1.0f + expf(-x)); }

// ---------------- init ----------------
__global__ void k_init() {
    int i = blockIdx.x * blockDim.x + threadIdx.x;
    if (i < Bn * Hn) { d_CT[0][i] = 0.0f; d_CB[0][i] = 0.0f; }
    if (i < 8 * 32) d_barArr[i] = 0u;
}

// ---------------- token gate table ----------------
__global__ void k_gtab(const float* __restrict__ emb,
                       const float* __restrict__ Wfx, const float* __restrict__ bf,
                       const float* __restrict__ Wix, const float* __restrict__ bi,
                       const float* __restrict__ Wox, const float* __restrict__ bo,
                       const float* __restrict__ Wcx, const float* __restrict__ bc) {
    __shared__ float es[In];
    int v = blockIdx.x;
    int tid = threadIdx.x;                // 256
    if (tid < In) es[tid] = emb[v * In + tid];
    __syncthreads();
    for (int h = tid; h < Hn; h += 256) {
        float af = bf[h], ai = bi[h], ao = bo[h], ac = bc[h];
        #pragma unroll 4
        for (int k = 0; k < In; k++) {
            float e = es[k];
            af = fmaf(e, Wfx[k * Hn + h], af);
            ai = fmaf(e, Wix[k * Hn + h], ai);
            ao = fmaf(e, Wox[k * Hn + h], ao);
            ac = fmaf(e, Wcx[k * Hn + h], ac);
        }
        d_gtab[v * 2048 + h]        = af;
        d_gtab[v * 2048 + 512 + h]  = ai;
        d_gtab[v * 2048 + 1024 + h] = ao;
        d_gtab[v * 2048 + 1536 + h] = sigf(ac);   // c_tilde pre-sigmoid (no recurrent term)
    }
}

// ---------------- pack Wfc/Wic interleaved by output column ----------------
__global__ void k_wpack(const float* __restrict__ Wfc, const float* __restrict__ Wic) {
    int i = blockIdx.x * blockDim.x + threadIdx.x;   // over H*H
    if (i < Hn * Hn) {
        int k = i / Hn, h = i % Hn;
        d_Wpack[k * 1024 + 2 * h]     = Wfc[i];
        d_Wpack[k * 1024 + 2 * h + 1] = Wic[i];
    }
}

// ---------------- persistent recurrent kernel (weight-stationary registers) ----------------
__global__ void __launch_bounds__(THR_R, 1) k_recur(const int* __restrict__ xIdx) {
    extern __shared__ float sm[];
    ull*   Asd = (ull*)sm;                  // [16 warp][16 r][32 kk] dup pairs (64KB)
    float* Ps  = sm + ASD_ULL * 2;          // [16 slot][16 r][64 c]           (64KB)

    const int tid = threadIdx.x;
    const int bx  = blockIdx.x;
    const int rb  = bx >> 4;              // 0..7  row tile (16 batches)
    const int cb  = bx & 15;              // 0..15 col tile (32 h-units)
    const int b0  = rb * 16;
    const int u0  = cb * 32;
    const int n0  = cb * 64;

    const int wid  = tid >> 5;            // 0..15
    const int lane = tid & 31;
    const int ks   = wid * 32;            // this warp's K-slice (32 k)

    // ---- weight-stationary: lane's (f,i) column pair for all 32 k of this slice ----
    ull B2[32];
    #pragma unroll
    for (int kk = 0; kk < 32; kk++)
        B2[kk] = *(const ull*)(d_Wpack + (ks + kk) * 1024 + n0 + 2 * lane);

    // staging indices: lane covers row r (of 16), k-half hf (16 k each)
    const int sr = lane >> 1;
    const int hf = lane & 1;

    // epilogue: one (row er, h-unit eu) per thread
    const int er  = tid & 15;             // 0..15
    const int eu  = tid >> 4;             // 0..31
    const int eb  = b0 + er;

    unsigned int* barp = &d_barArr[rb * 32];
    ull* AsW = Asd + wid * 512;           // this warp's [16 r][32 kk] dup region

    #pragma unroll 1
    for (int t = 0; t < Tn; t++) {
        const float* CBsrc = d_CB[t & 1];
        const float* CTsrc = d_CT[t & 1];

        // ---- prefetch token, gate-table values, Cold ----
        int   tok  = xIdx[eb * Tn + t];
        float gf0  = d_gtab[tok * 2048 + u0 + eu];
        float gi0  = d_gtab[tok * 2048 + 512 + u0 + eu];
        float ct0  = d_gtab[tok * 2048 + 1536 + u0 + eu];
        float Cold = __ldcg(&CTsrc[(u0 + eu) * Bn + eb]);

        // ---- warp-local staging of this warp's A slice, PRE-DUPLICATED ----
        // Asd[r][kk] = (C[b0+r][ks+kk], same)  -- straight reads from row-major CB
        {
            const float* src = CBsrc + (b0 + sr) * Hn + ks + hf * 16;
            ull* dst = AsW + sr * 32 + hf * 16;
            #pragma unroll
            for (int j = 0; j < 4; j++) {
                float4 v = __ldcg((const float4*)(src + 4 * j));
                ull u0d, u1d, u2d, u3d;
                PACK_DUP(u0d, v.x); PACK_DUP(u1d, v.y);
                PACK_DUP(u2d, v.z); PACK_DUP(u3d, v.w);
                *(ulonglong2*)(dst + 4 * j)     = make_ulonglong2(u0d, u1d);
                *(ulonglong2*)(dst + 4 * j + 2) = make_ulonglong2(u2d, u3d);
            }
        }
        __syncwarp();

        // ---- GEMM: per lane, 16 rows x 1 colpair over the warp's 32-k slice ----
        // A loads are all-lane broadcast LDS.128 (conflict-free, 16B requested)
        #pragma unroll
        for (int rp = 0; rp < 8; rp++) {
            const ull* A0 = AsW + (2 * rp) * 32;
            const ull* A1 = A0 + 32;
            ull acc0 = 0ull, acc1 = 0ull;
            #pragma unroll
            for (int kq = 0; kq < 16; kq++) {
                ulonglong2 d0 = *(const ulonglong2*)(A0 + 2 * kq);
                ulonglong2 d1 = *(const ulonglong2*)(A1 + 2 * kq);
                FMA2(acc0, d0.x, B2[2 * kq]); FMA2(acc0, d0.y, B2[2 * kq + 1]);
                FMA2(acc1, d1.x, B2[2 * kq]); FMA2(acc1, d1.y, B2[2 * kq + 1]);
            }
            *(ull*)(Ps + wid * 1024 + (2 * rp) * 64 + 2 * lane)     = acc0;
            *(ull*)(Ps + wid * 1024 + (2 * rp + 1) * 64 + 2 * lane) = acc1;
        }
        __syncthreads();

        // ---- tree-reduce 16 slots + gate epilogue + dual C store ----
        float* CTdst = d_CT[(t + 1) & 1];
        float* CBdst = d_CB[(t + 1) & 1];
        {
            const ull* pp = (const ull*)Ps + er * 32 + eu;
            ull s0 = 0ull, s1 = 0ull, s2 = 0ull, s3 = 0ull;
            #pragma unroll
            for (int w = 0; w < 16; w += 4) {
                ull v0 = pp[(w + 0) * 512];
                ull v1 = pp[(w + 1) * 512];
                ull v2 = pp[(w + 2) * 512];
                ull v3 = pp[(w + 3) * 512];
                ADD2(s0, v0); ADD2(s1, v1); ADD2(s2, v2); ADD2(s3, v3);
            }
            ADD2(s0, s1); ADD2(s2, s3); ADD2(s0, s2);
            float sf = __uint_as_float((unsigned)(s0 & 0xffffffffu));
            float si = __uint_as_float((unsigned)(s0 >> 32));
            float f  = sigf(gf0 + sf);
            float ig = sigf(gi0 + si);
            float Cn = (tok > 0) ? fmaf(Cold, f, ct0 * ig) : 0.0f;
            __stcg(&CTdst[(u0 + eu) * Bn + eb], Cn);
            __stcg(&CBdst[eb * Hn + u0 + eu], Cn);
        }

        // ---- row-group barrier (16 blocks share this counter) ----
        __syncthreads();
        if (tid == 0) {
            __threadfence();                       // release C writes
            atomicAdd(barp, 1u);
            unsigned target = (unsigned)(t + 1) * 16u;
            while (*((volatile unsigned int*)barp) < target) { __nanosleep(20); }
            __threadfence();                       // acquire
        }
        __syncthreads();
    }
}

// ---------------- final: o gate + h = tanh(C_T)*o ----------------
__global__ void k_final_h(const int* __restrict__ xIdx, const float* __restrict__ Woc) {
    __shared__ float cps[Hn];
    int b = blockIdx.x;
    int tid = threadIdx.x;                         // 128
    const float* CTprev = d_CT[(Tn - 1) & 1];      // C_{T-1}, [h][b]
    const float* CTlast = d_CT[Tn & 1];            // C_T,     [h][b]
    for (int k = tid; k < Hn; k += 128) cps[k] = CTprev[k * Bn + b];
    __syncthreads();
    int tok = xIdx[b * Tn + (Tn - 1)];
    float acc[4] = {0.f, 0.f, 0.f, 0.f};
    #pragma unroll 4
    for (int k = 0; k < Hn; k++) {
        float c = cps[k];
        const float* wr = Woc + k * Hn + tid;
        acc[0] = fmaf(c, wr[0],   acc[0]);
        acc[1] = fmaf(c, wr[128], acc[1]);
        acc[2] = fmaf(c, wr[256], acc[2]);
        acc[3] = fmaf(c, wr[384], acc[3]);
    }
    #pragma unroll
    for (int m = 0; m < 4; m++) {
        int h = tid + m * 128;
        float o = sigf(d_gtab[tok * 2048 + 1024 + h] + acc[m]);
        d_Hf[b * Hn + h] = tanhf(CTlast[h * Bn + b]) * o;
    }
}

// ---------------- final: logits + log_softmax ----------------
__global__ void k_final_p(const float* __restrict__ Wph, const float* __restrict__ bp,
                          float* __restrict__ out) {
    __shared__ float hs[Hn];
    __shared__ float red[128];
    int b = blockIdx.x;
    int tid = threadIdx.x;                         // 128
    for (int k = tid; k < Hn; k += 128) hs[k] = d_Hf[b * Hn + k];
    __syncthreads();
    float p = -INFINITY;
    if (tid < NCn) {
        p = bp[tid];
        #pragma unroll 4
        for (int k = 0; k < Hn; k++) p = fmaf(hs[k], Wph[k * NCn + tid], p);
    }
    red[tid] = p;
    __syncthreads();
    for (int s = 64; s > 0; s >>= 1) {
        if (tid < s) red[tid] = fmaxf(red[tid], red[tid + s]);
        __syncthreads();
    }
    float mx = red[0];
    __syncthreads();
    red[tid] = (tid < NCn) ? expf(p - mx) : 0.0f;
    __syncthreads();
    for (int s = 64; s > 0; s >>= 1) {
        if (tid < s) red[tid] += red[tid + s];
        __syncthreads();
    }
    float lse = mx + logf(red[0]);
    if (tid < NCn) out[b * NCn + tid] = p - lse;
}

// ---------------- launch ----------------
extern "C" void kernel_launch(void* const* d_in, const int* in_sizes, int n_in,
                              void* d_out, int out_size) {
    (void)in_sizes; (void)n_in; (void)out_size;
    const int*   x   = (const int*)  d_in[0];
    const float* emb = (const float*)d_in[1];
    const float* Wfx = (const float*)d_in[2];
    const float* Wfc = (const float*)d_in[3];
    const float* bf  = (const float*)d_in[4];
    const float* Wix = (const float*)d_in[5];
    const float* Wic = (const float*)d_in[6];
    const float* bi  = (const float*)d_in[7];
    const float* Wox = (const float*)d_in[8];
    const float* Woc = (const float*)d_in[9];
    const float* bo  = (const float*)d_in[10];
    const float* Wcx = (const float*)d_in[11];
    const float* bc  = (const float*)d_in[12];
    const float* Wph = (const float*)d_in[13];
    const float* bp  = (const float*)d_in[14];
    float* out = (float*)d_out;

    cudaFuncSetAttribute(k_recur, cudaFuncAttributeMaxDynamicSharedMemorySize, SMEM_R_BYTES);

    k_init<<<(Bn * Hn + 255) / 256, 256>>>();
    k_gtab<<<Vn, 256>>>(emb, Wfx, bf, Wix, bi, Wox, bo, Wcx, bc);
    k_wpack<<<(Hn * Hn + 255) / 256, 256>>>(Wfc, Wic);
    k_recur<<<GRID_R, THR_R, SMEM_R_BYTES>>>(x);
    k_final_h<<<Bn, 128>>>(x, Woc);
    k_final_p<<<Bn, 128>>>(Wph, bp, out);
}

// round 15
// speedup vs baseline: 4.0109x; 4.0109x over previous
#include <cuda_runtime.h>
#include <cuda_bf16.h>
#include <cstdint>

// Problem constants
#define Bn  128
#define Tn  512
#define In  128
#define Hn  512
#define NCn 100
#define Vn  101

// k_recur: 128 blocks = 8 row-tiles (16 batches) x 16 col-tiles (32 h-units)
#define GRID_R 128
#define THR_R  512        // 16 warps; warp w owns ksteps {2w, 2w+1} (32 k of 512)

// smem layout (bytes)
#define BS_BYTES  131072                  // B frags: [32 kstep][8 nt][2 s][32 lane] ull
#define AS_BYTES  32768                   // A frags: [32 kstep][2 s][32 lane] uint4
#define PS_ROW    66                      // padded floats per row (bank-conflict-free)
#define PS_FLOATS (16 * 16 * PS_ROW)      // 16 slots x 16 rows x 66
#define SMEM_R_BYTES (BS_BYTES + AS_BYTES + PS_FLOATS * 4)   // 231424 B

typedef unsigned long long ull;

#define ADD2(accv, bv) \
    asm("add.rn.f32x2 %0, %0, %1;" : "+l"(accv) : "l"(bv))

// ---------------- device-global scratch ----------------
__device__ float          d_gtab[Vn * 4 * Hn];     // [tok][f,i,o,sig(c)][h]
__device__ ull            d_Bfrag[16 * 32 * 8 * 2 * 32];          // W frags (2MB)
__device__ __nv_bfloat16  d_Afrag[2][8 * 32 * 2 * 32 * 8];        // C frags, dbl-buffered
__device__ float          d_CT[2][Hn * Bn];        // fp32 cell state [h][b]
__device__ float          d_Hf[Bn * Hn];
__device__ unsigned int   d_barArr[8 * 32];

__device__ __forceinline__ float sigf(float x) { return 1.0f / (1.0f + expf(-x)); }

__device__ __forceinline__ void mma_bf16(float* d, const uint4 a, const ull b) {
    unsigned b0 = (unsigned)(b & 0xffffffffull);
    unsigned b1 = (unsigned)(b >> 32);
    asm volatile(
        "mma.sync.aligned.m16n8k16.row.col.f32.bf16.bf16.f32 "
        "{%0,%1,%2,%3}, {%4,%5,%6,%7}, {%8,%9}, {%0,%1,%2,%3};"
        : "+f"(d[0]), "+f"(d[1]), "+f"(d[2]), "+f"(d[3])
        : "r"(a.x), "r"(a.y), "r"(a.z), "r"(a.w), "r"(b0), "r"(b1));
}

// ---------------- init: zero C0 state, A frags (parity 0), barriers ----------------
__global__ void k_init() {
    int i = blockIdx.x * blockDim.x + threadIdx.x;
    if (i < Bn * Hn) d_CT[0][i] = 0.0f;
    if (i < 65536) ((unsigned*)d_Afrag)[i] = 0u;   // 131072 bf16 zeros = parity 0
    if (i < 8 * 32) d_barArr[i] = 0u;
}

// ---------------- token gate table ----------------
__global__ void k_gtab(const float* __restrict__ emb,
                       const float* __restrict__ Wfx, const float* __restrict__ bf,
                       const float* __restrict__ Wix, const float* __restrict__ bi,
                       const float* __restrict__ Wox, const float* __restrict__ bo,
                       const float* __restrict__ Wcx, const float* __restrict__ bc) {
    __shared__ float es[In];
    int v = blockIdx.x;
    int tid = threadIdx.x;                // 256
    if (tid < In) es[tid] = emb[v * In + tid];
    __syncthreads();
    for (int h = tid; h < Hn; h += 256) {
        float af = bf[h], ai = bi[h], ao = bo[h], ac = bc[h];
        #pragma unroll 4
        for (int k = 0; k < In; k++) {
            float e = es[k];
            af = fmaf(e, Wfx[k * Hn + h], af);
            ai = fmaf(e, Wix[k * Hn + h], ai);
            ao = fmaf(e, Wox[k * Hn + h], ao);
            ac = fmaf(e, Wcx[k * Hn + h], ac);
        }
        d_gtab[v * 2048 + h]        = af;
        d_gtab[v * 2048 + 512 + h]  = ai;
        d_gtab[v * 2048 + 1024 + h] = ao;
        d_gtab[v * 2048 + 1536 + h] = sigf(ac);   // c_tilde pre-sigmoid
    }
}

// ---------------- W hi/lo split -> mma B fragments ----------------
// d_Bfrag[cb][kstep][nt][s][lane] : b0 = {W[k0+2tg][n], W[k0+2tg+1][n]}, b1 = +8
// packed col n = 2h + gate (gate0=f from Wfc, gate1=i from Wic); n = cb*64 + nt*8 + g
__global__ void k_wsplit(const float* __restrict__ Wfc, const float* __restrict__ Wic) {
    int gid = blockIdx.x * blockDim.x + threadIdx.x;   // 262144
    if (gid >= 16 * 32 * 8 * 2 * 32) return;
    int lane  = gid & 31;
    int s     = (gid >> 5) & 1;
    int nt    = (gid >> 6) & 7;
    int kstep = (gid >> 9) & 31;
    int cb    = gid >> 14;
    int g  = lane >> 2;
    int tg = lane & 3;
    int n  = cb * 64 + nt * 8 + g;
    int h  = n >> 1;
    const float* Wsrc = (n & 1) ? Wic : Wfc;
    int k0 = kstep * 16 + 2 * tg;
    unsigned words[2];
    #pragma unroll
    for (int half8 = 0; half8 < 2; half8++) {
        float v0 = Wsrc[(k0 + half8 * 8) * Hn + h];
        float v1 = Wsrc[(k0 + half8 * 8 + 1) * Hn + h];
        __nv_bfloat16 e0, e1;
        if (s == 0) { e0 = __float2bfloat16(v0); e1 = __float2bfloat16(v1); }
        else {
            __nv_bfloat16 h0 = __float2bfloat16(v0), h1 = __float2bfloat16(v1);
            e0 = __float2bfloat16(v0 - __bfloat162float(h0));
            e1 = __float2bfloat16(v1 - __bfloat162float(h1));
        }
        unsigned w = ((unsigned)*(unsigned short*)&e1 << 16) | (unsigned)*(unsigned short*)&e0;
        words[half8] = w;
    }
    d_Bfrag[gid] = ((ull)words[1] << 32) | (ull)words[0];
}

// ---------------- persistent recurrent kernel (tensor-core mma) ----------------
__global__ void __launch_bounds__(THR_R, 1) k_recur(const int* __restrict__ xIdx) {
    extern __shared__ char smraw[];
    ull*   Bs = (ull*)smraw;                         // [kstep][nt][s][lane]
    uint4* As = (uint4*)(smraw + BS_BYTES);          // [kstep][s][lane]
    float* Ps = (float*)(smraw + BS_BYTES + AS_BYTES); // [16 slot][16 r][66]

    const int tid = threadIdx.x;
    const int bx  = blockIdx.x;
    const int rb  = bx >> 4;              // 0..7  row tile (16 batches)
    const int cb  = bx & 15;              // 0..15 col tile (32 h-units)
    const int b0  = rb * 16;
    const int u0  = cb * 32;

    const int wid  = tid >> 5;            // 0..15
    const int lane = tid & 31;
    const int g    = lane >> 2;
    const int tg   = lane & 3;

    // Stage resident B fragments for this col-tile (128KB) once
    {
        const uint4* src = (const uint4*)(d_Bfrag + (size_t)cb * 16384);
        #pragma unroll
        for (int i = 0; i < 16; i++) {
            int li = tid + i * THR_R;     // 0..8191
            ((uint4*)Bs)[li] = src[li];
        }
    }
    __syncthreads();

    // epilogue: one (row er, h-unit eu) per thread
    const int er  = tid & 15;             // 0..15
    const int eu  = tid >> 4;             // 0..31
    const int eb  = b0 + er;
    // A-fragment write coordinates for (er, h=u0+eu)
    const int eh     = u0 + eu;
    const int ekstep = eh >> 4;
    const int ec     = eh & 15;
    const int elane  = (er & 7) * 4 + ((ec & 7) >> 1);
    const int ereg   = (er >> 3) + (((ec >> 3) & 1) << 1);
    const int ehalf  = ec & 1;
    // halfword offset within [kstep][s=0][lane][8]
    const int eoff   = (ekstep * 2) * 256 + elane * 8 + ereg * 2 + ehalf;

    unsigned int* barp = &d_barArr[rb * 32];

    #pragma unroll 1
    for (int t = 0; t < Tn; t++) {
        const int p  = t & 1;
        const int p1 = (t + 1) & 1;

        // ---- prefetch token, gate-table values, Cold ----
        int   tok  = xIdx[eb * Tn + t];
        float gf0  = d_gtab[tok * 2048 + u0 + eu];
        float gi0  = d_gtab[tok * 2048 + 512 + u0 + eu];
        float ct0  = d_gtab[tok * 2048 + 1536 + u0 + eu];
        float Cold = __ldcg(&d_CT[p][(u0 + eu) * Bn + eb]);

        // ---- stage this row-tile's A fragments (32KB) ----
        {
            const uint4* src = (const uint4*)(d_Afrag[p] + (size_t)rb * 16384);
            #pragma unroll
            for (int i = 0; i < 4; i++) {
                int li = tid + i * THR_R;     // 0..2047
                As[li] = __ldcg(src + li);
            }
        }
        __syncthreads();

        // ---- GEMM: warp w covers ksteps {2w, 2w+1}, 3-term hi/lo mma ----
        float acc[8][4];
        #pragma unroll
        for (int nt = 0; nt < 8; nt++)
            #pragma unroll
            for (int q = 0; q < 4; q++) acc[nt][q] = 0.0f;

        #pragma unroll
        for (int ks2 = 0; ks2 < 2; ks2++) {
            const int kstep = 2 * wid + ks2;
            uint4 ah = As[(kstep * 2 + 0) * 32 + lane];
            uint4 al = As[(kstep * 2 + 1) * 32 + lane];
            const ull* bbase = Bs + (size_t)kstep * 512 + lane;
            #pragma unroll
            for (int nt = 0; nt < 8; nt++) {
                ull bh = bbase[(nt * 2 + 0) * 32];
                ull bl = bbase[(nt * 2 + 1) * 32];
                mma_bf16(acc[nt], ah, bh);   // Ch * Wh
                mma_bf16(acc[nt], al, bh);   // Cl * Wh
                mma_bf16(acc[nt], ah, bl);   // Ch * Wl
            }
        }

        // ---- store per-warp partials: D rows {g, g+8}, cols nt*8 + {2tg, 2tg+1} ----
        {
            float* base = Ps + wid * (16 * PS_ROW);
            #pragma unroll
            for (int nt = 0; nt < 8; nt++) {
                *(float2*)(base + g * PS_ROW + nt * 8 + 2 * tg)       =
                    make_float2(acc[nt][0], acc[nt][1]);
                *(float2*)(base + (g + 8) * PS_ROW + nt * 8 + 2 * tg) =
                    make_float2(acc[nt][2], acc[nt][3]);
            }
        }
        __syncthreads();

        // ---- tree-reduce 16 slots + gate epilogue + state stores ----
        {
            const ull* pp = (const ull*)Ps + er * (PS_ROW / 2) + eu;
            const int SS = 16 * PS_ROW / 2;     // slot stride in ull (= 528)
            ull s0 = 0ull, s1 = 0ull, s2 = 0ull, s3 = 0ull;
            #pragma unroll
            for (int w = 0; w < 16; w += 4) {
                ull v0 = pp[(w + 0) * SS];
                ull v1 = pp[(w + 1) * SS];
                ull v2 = pp[(w + 2) * SS];
                ull v3 = pp[(w + 3) * SS];
                ADD2(s0, v0); ADD2(s1, v1); ADD2(s2, v2); ADD2(s3, v3);
            }
            ADD2(s0, s1); ADD2(s2, s3); ADD2(s0, s2);
            float sf = __uint_as_float((unsigned)(s0 & 0xffffffffu));
            float si = __uint_as_float((unsigned)(s0 >> 32));
            float f  = sigf(gf0 + sf);
            float ig = sigf(gi0 + si);
            float Cn = (tok > 0) ? fmaf(Cold, f, ct0 * ig) : 0.0f;
            // fp32 state (exact carry)
            __stcg(&d_CT[p1][(u0 + eu) * Bn + eb], Cn);
            // hi/lo bf16 scattered into next step's A fragments
            __nv_bfloat16 chi = __float2bfloat16(Cn);
            __nv_bfloat16 clo = __float2bfloat16(Cn - __bfloat162float(chi));
            __nv_bfloat16* ap = d_Afrag[p1] + (size_t)rb * 16384 + eoff;
            ap[0]   = chi;     // s=0 plane
            ap[256] = clo;     // s=1 plane (+32 lanes * 8 halves)
        }

        // ---- row-group barrier (16 blocks share this counter) ----
        __syncthreads();
        if (tid == 0) {
            __threadfence();
            atomicAdd(barp, 1u);
            unsigned target = (unsigned)(t + 1) * 16u;
            while (*((volatile unsigned int*)barp) < target) { __nanosleep(20); }
            __threadfence();
        }
        __syncthreads();
    }
}

// ---------------- final: o gate + h = tanh(C_T)*o ----------------
__global__ void k_final_h(const int* __restrict__ xIdx, const float* __restrict__ Woc) {
    __shared__ float cps[Hn];
    int b = blockIdx.x;
    int tid = threadIdx.x;                         // 128
    const float* CTprev = d_CT[(Tn - 1) & 1];      // C_{T-1}, [h][b]
    const float* CTlast = d_CT[Tn & 1];            // C_T
    for (int k = tid; k < Hn; k += 128) cps[k] = CTprev[k * Bn + b];
    __syncthreads();
    int tok = xIdx[b * Tn + (Tn - 1)];
    float acc[4] = {0.f, 0.f, 0.f, 0.f};
    #pragma unroll 4
    for (int k = 0; k < Hn; k++) {
        float c = cps[k];
        const float* wr = Woc + k * Hn + tid;
        acc[0] = fmaf(c, wr[0],   acc[0]);
        acc[1] = fmaf(c, wr[128], acc[1]);
        acc[2] = fmaf(c, wr[256], acc[2]);
        acc[3] = fmaf(c, wr[384], acc[3]);
    }
    #pragma unroll
    for (int m = 0; m < 4; m++) {
        int h = tid + m * 128;
        float o = sigf(d_gtab[tok * 2048 + 1024 + h] + acc[m]);
        d_Hf[b * Hn + h] = tanhf(CTlast[h * Bn + b]) * o;
    }
}

// ---------------- final: logits + log_softmax ----------------
__global__ void k_final_p(const float* __restrict__ Wph, const float* __restrict__ bp,
                          float* __restrict__ out) {
    __shared__ float hs[Hn];
    __shared__ float red[128];
    int b = blockIdx.x;
    int tid = threadIdx.x;                         // 128
    for (int k = tid; k < Hn; k += 128) hs[k] = d_Hf[b * Hn + k];
    __syncthreads();
    float p = -INFINITY;
    if (tid < NCn) {
        p = bp[tid];
        #pragma unroll 4
        for (int k = 0; k < Hn; k++) p = fmaf(hs[k], Wph[k * NCn + tid], p);
    }
    red[tid] = p;
    __syncthreads();
    for (int s = 64; s > 0; s >>= 1) {
        if (tid < s) red[tid] = fmaxf(red[tid], red[tid + s]);
        __syncthreads();
    }
    float mx = red[0];
    __syncthreads();
    red[tid] = (tid < NCn) ? expf(p - mx) : 0.0f;
    __syncthreads();
    for (int s = 64; s > 0; s >>= 1) {
        if (tid < s) red[tid] += red[tid + s];
        __syncthreads();
    }
    float lse = mx + logf(red[0]);
    if (tid < NCn) out[b * NCn + tid] = p - lse;
}

// ---------------- launch ----------------
extern "C" void kernel_launch(void* const* d_in, const int* in_sizes, int n_in,
                              void* d_out, int out_size) {
    (void)in_sizes; (void)n_in; (void)out_size;
    const int*   x   = (const int*)  d_in[0];
    const float* emb = (const float*)d_in[1];
    const float* Wfx = (const float*)d_in[2];
    const float* Wfc = (const float*)d_in[3];
    const float* bf  = (const float*)d_in[4];
    const float* Wix = (const float*)d_in[5];
    const float* Wic = (const float*)d_in[6];
    const float* bi  = (const float*)d_in[7];
    const float* Wox = (const float*)d_in[8];
    const float* Woc = (const float*)d_in[9];
    const float* bo  = (const float*)d_in[10];
    const float* Wcx = (const float*)d_in[11];
    const float* bc  = (const float*)d_in[12];
    const float* Wph = (const float*)d_in[13];
    const float* bp  = (const float*)d_in[14];
    float* out = (float*)d_out;

    cudaFuncSetAttribute(k_recur, cudaFuncAttributeMaxDynamicSharedMemorySize, SMEM_R_BYTES);

    k_init<<<(131072 + 255) / 256, 256>>>();
    k_gtab<<<Vn, 256>>>(emb, Wfx, bf, Wix, bi, Wox, bo, Wcx, bc);
    k_wsplit<<<(16 * 32 * 8 * 2 * 32 + 255) / 256, 256>>>(Wfc, Wic);
    k_recur<<<GRID_R, THR_R, SMEM_R_BYTES>>>(x);
    k_final_h<<<Bn, 128>>>(x, Woc);
    k_final_p<<<Bn, 128>>>(Wph, bp, out);
}

// round 16
// speedup vs baseline: 5.1370x; 1.2808x over previous
#include <cuda_runtime.h>
#include <cuda_bf16.h>
#include <cstdint>

// Problem constants
#define Bn  128
#define Tn  512
#define In  128
#define Hn  512
#define NCn 100
#define Vn  101

// k_recur: 128 blocks = 8 row-tiles (16 batches) x 16 col-tiles (32 h-units)
#define GRID_R 128
#define THR_R  512        // 16 warps = (8 kslices) x (2 n-halves)

// smem layout (bytes)
#define BS_BYTES  131072                  // B frags: [32 kstep][8 nt][2 s][32 lane] ull
#define PS_ROW    34                      // padded floats per row (32 cols used)
#define PS_FLOATS (16 * 16 * PS_ROW)      // 16 slots x 16 rows x 34  (34816 B)
#define ASTG_OFF  (BS_BYTES + PS_FLOATS * 4)
#define SMEM_R_BYTES (ASTG_OFF + 2048)    // + 2KB A-frag writeback staging

typedef unsigned long long ull;

#define ADD2(accv, bv) \
    asm("add.rn.f32x2 %0, %0, %1;" : "+l"(accv) : "l"(bv))

// ---------------- device-global scratch ----------------
__device__ float          d_gtab[Vn * 4 * Hn];     // [tok][f,i,o,sig(c)][h]
__device__ ull            d_Bfrag[16 * 32 * 8 * 2 * 32];          // W frags (2MB)
__device__ __nv_bfloat16  d_Afrag[2][8 * 32 * 2 * 32 * 8];        // C frags, dbl-buffered
__device__ float          d_CT[2][Hn * Bn];        // fp32 cell state [h][b]
__device__ float          d_Hf[Bn * Hn];
__device__ unsigned int   d_barArr[8 * 32];

__device__ __forceinline__ float sigf(float x) { return 1.0f / (1.0f + expf(-x)); }

__device__ __forceinline__ void mma_bf16(float* d, const uint4 a, const ull b) {
    unsigned b0 = (unsigned)(b & 0xffffffffull);
    unsigned b1 = (unsigned)(b >> 32);
    asm volatile(
        "mma.sync.aligned.m16n8k16.row.col.f32.bf16.bf16.f32 "
        "{%0,%1,%2,%3}, {%4,%5,%6,%7}, {%8,%9}, {%0,%1,%2,%3};"
        : "+f"(d[0]), "+f"(d[1]), "+f"(d[2]), "+f"(d[3])
        : "r"(a.x), "r"(a.y), "r"(a.z), "r"(a.w), "r"(b0), "r"(b1));
}

// ---------------- init: zero C0 state, A frags (parity 0), barriers ----------------
__global__ void k_init() {
    int i = blockIdx.x * blockDim.x + threadIdx.x;
    if (i < Bn * Hn) d_CT[0][i] = 0.0f;
    if (i < 65536) ((unsigned*)d_Afrag)[i] = 0u;   // 131072 bf16 zeros = parity 0
    if (i < 8 * 32) d_barArr[i] = 0u;
}

// ---------------- token gate table ----------------
__global__ void k_gtab(const float* __restrict__ emb,
                       const float* __restrict__ Wfx, const float* __restrict__ bf,
                       const float* __restrict__ Wix, const float* __restrict__ bi,
                       const float* __restrict__ Wox, const float* __restrict__ bo,
                       const float* __restrict__ Wcx, const float* __restrict__ bc) {
    __shared__ float es[In];
    int v = blockIdx.x;
    int tid = threadIdx.x;                // 256
    if (tid < In) es[tid] = emb[v * In + tid];
    __syncthreads();
    for (int h = tid; h < Hn; h += 256) {
        float af = bf[h], ai = bi[h], ao = bo[h], ac = bc[h];
        #pragma unroll 4
        for (int k = 0; k < In; k++) {
            float e = es[k];
            af = fmaf(e, Wfx[k * Hn + h], af);
            ai = fmaf(e, Wix[k * Hn + h], ai);
            ao = fmaf(e, Wox[k * Hn + h], ao);
            ac = fmaf(e, Wcx[k * Hn + h], ac);
        }
        d_gtab[v * 2048 + h]        = af;
        d_gtab[v * 2048 + 512 + h]  = ai;
        d_gtab[v * 2048 + 1024 + h] = ao;
        d_gtab[v * 2048 + 1536 + h] = sigf(ac);   // c_tilde pre-sigmoid
    }
}

// ---------------- W hi/lo split -> mma B fragments ----------------
// d_Bfrag[cb][kstep][nt][s][lane]; packed col n = 2h + gate (0:f, 1:i)
__global__ void k_wsplit(const float* __restrict__ Wfc, const float* __restrict__ Wic) {
    int gid = blockIdx.x * blockDim.x + threadIdx.x;   // 262144
    if (gid >= 16 * 32 * 8 * 2 * 32) return;
    int lane  = gid & 31;
    int s     = (gid >> 5) & 1;
    int nt    = (gid >> 6) & 7;
    int kstep = (gid >> 9) & 31;
    int cb    = gid >> 14;
    int g  = lane >> 2;
    int tg = lane & 3;
    int n  = cb * 64 + nt * 8 + g;
    int h  = n >> 1;
    const float* Wsrc = (n & 1) ? Wic : Wfc;
    int k0 = kstep * 16 + 2 * tg;
    unsigned words[2];
    #pragma unroll
    for (int half8 = 0; half8 < 2; half8++) {
        float v0 = Wsrc[(k0 + half8 * 8) * Hn + h];
        float v1 = Wsrc[(k0 + half8 * 8 + 1) * Hn + h];
        __nv_bfloat16 e0, e1;
        if (s == 0) { e0 = __float2bfloat16(v0); e1 = __float2bfloat16(v1); }
        else {
            __nv_bfloat16 h0 = __float2bfloat16(v0), h1 = __float2bfloat16(v1);
            e0 = __float2bfloat16(v0 - __bfloat162float(h0));
            e1 = __float2bfloat16(v1 - __bfloat162float(h1));
        }
        unsigned w = ((unsigned)*(unsigned short*)&e1 << 16) | (unsigned)*(unsigned short*)&e0;
        words[half8] = w;
    }
    d_Bfrag[gid] = ((ull)words[1] << 32) | (ull)words[0];
}

// ---------------- persistent recurrent kernel (tensor-core mma) ----------------
__global__ void __launch_bounds__(THR_R, 1) k_recur(const int* __restrict__ xIdx) {
    extern __shared__ char smraw[];
    ull*   Bs   = (ull*)smraw;                       // [kstep][nt][s][lane]
    float* Ps   = (float*)(smraw + BS_BYTES);        // [16 slot][16 r][34]
    __nv_bfloat16* Astg = (__nv_bfloat16*)(smraw + ASTG_OFF);  // [2 lk][2 s][256]

    const int tid = threadIdx.x;
    const int bx  = blockIdx.x;
    const int rb  = bx >> 4;              // 0..7  row tile (16 batches)
    const int cb  = bx & 15;              // 0..15 col tile (32 h-units)
    const int b0  = rb * 16;
    const int u0  = cb * 32;

    const int wid  = tid >> 5;            // 0..15
    const int lane = tid & 31;
    const int g    = lane >> 2;
    const int tg   = lane & 3;
    const int ks8  = wid >> 1;            // 0..7   4-kstep slice
    const int nh   = wid & 1;             // 0..1   n-half (4 nt)
    const int k0   = ks8 * 4;

    // Stage resident B fragments for this col-tile (128KB) once
    {
        const uint4* src = (const uint4*)(d_Bfrag + (size_t)cb * 16384);
        #pragma unroll
        for (int i = 0; i < 16; i++) {
            int li = tid + i * THR_R;     // 0..8191
            ((uint4*)Bs)[li] = src[li];
        }
    }
    __syncthreads();

    // epilogue: one (row er, h-unit eu) per thread
    const int er   = tid & 15;            // 0..15
    const int eu   = tid >> 4;            // 0..31
    const int eb   = b0 + er;
    const int nh_e = eu >> 4;             // which n-half my column lives in
    // A-fragment staging coordinates for (er, h=u0+eu)
    const int ec     = eu & 15;
    const int elane  = (er & 7) * 4 + ((ec & 7) >> 1);
    const int ereg   = (er >> 3) + (((ec >> 3) & 1) << 1);
    const int ehalf  = ec & 1;
    const int eoff   = (nh_e * 2) * 256 + elane * 8 + ereg * 2 + ehalf;  // s=0 plane

    unsigned int* barp = &d_barArr[rb * 32];

    #pragma unroll 1
    for (int t = 0; t < Tn; t++) {
        const int p  = t & 1;
        const int p1 = (t + 1) & 1;

        // ---- prefetch token, gate-table values, Cold ----
        int   tok  = xIdx[eb * Tn + t];
        float gf0  = d_gtab[tok * 2048 + u0 + eu];
        float gi0  = d_gtab[tok * 2048 + 512 + u0 + eu];
        float ct0  = d_gtab[tok * 2048 + 1536 + u0 + eu];
        float Cold = __ldcg(&d_CT[p][(u0 + eu) * Bn + eb]);

        // ---- direct-LDG A fragments for this warp's 4 ksteps (coalesced) ----
        const uint4* Afp = (const uint4*)(d_Afrag[p] + (size_t)rb * 16384);
        uint4 ah[4], al[4];
        #pragma unroll
        for (int kq = 0; kq < 4; kq++) {
            ah[kq] = __ldcg(Afp + ((k0 + kq) * 2 + 0) * 32 + lane);
            al[kq] = __ldcg(Afp + ((k0 + kq) * 2 + 1) * 32 + lane);
        }

        // ---- GEMM: 4 ksteps x 4 nt x 3 terms ----
        float acc[4][4];
        #pragma unroll
        for (int ntl = 0; ntl < 4; ntl++)
            #pragma unroll
            for (int q = 0; q < 4; q++) acc[ntl][q] = 0.0f;

        #pragma unroll
        for (int kq = 0; kq < 4; kq++) {
            const ull* bb = Bs + (size_t)(k0 + kq) * 512 + (4 * nh) * 64 + lane;
            #pragma unroll
            for (int ntl = 0; ntl < 4; ntl++) {
                ull bh = bb[ntl * 64];
                ull bl = bb[ntl * 64 + 32];
                mma_bf16(acc[ntl], ah[kq], bh);   // Ch * Wh
                mma_bf16(acc[ntl], al[kq], bh);   // Cl * Wh
                mma_bf16(acc[ntl], ah[kq], bl);   // Ch * Wl
            }
        }

        // ---- store per-warp partials: rows {g, g+8}, local cols ntl*8+2tg ----
        {
            float* base = Ps + wid * (16 * PS_ROW);
            #pragma unroll
            for (int ntl = 0; ntl < 4; ntl++) {
                *(float2*)(base + g * PS_ROW + ntl * 8 + 2 * tg)       =
                    make_float2(acc[ntl][0], acc[ntl][1]);
                *(float2*)(base + (g + 8) * PS_ROW + ntl * 8 + 2 * tg) =
                    make_float2(acc[ntl][2], acc[ntl][3]);
            }
        }
        __syncthreads();

        // ---- reduce 8 matching slots + gate epilogue + state stores ----
        {
            const ull* pp = (const ull*)Ps + nh_e * 272 + er * 17 + (eu & 15);
            ull s0 = 0ull, s1 = 0ull, s2 = 0ull, s3 = 0ull;
            #pragma unroll
            for (int j = 0; j < 8; j += 4) {
                ull v0 = pp[(j + 0) * 544];
                ull v1 = pp[(j + 1) * 544];
                ull v2 = pp[(j + 2) * 544];
                ull v3 = pp[(j + 3) * 544];
                ADD2(s0, v0); ADD2(s1, v1); ADD2(s2, v2); ADD2(s3, v3);
            }
            ADD2(s0, s1); ADD2(s2, s3); ADD2(s0, s2);
            float sf = __uint_as_float((unsigned)(s0 & 0xffffffffu));
            float si = __uint_as_float((unsigned)(s0 >> 32));
            float f  = sigf(gf0 + sf);
            float ig = sigf(gi0 + si);
            float Cn = (tok > 0) ? fmaf(Cold, f, ct0 * ig) : 0.0f;
            // fp32 state (exact carry)
            __stcg(&d_CT[p1][(u0 + eu) * Bn + eb], Cn);
            // hi/lo bf16 into smem staging (fragment order)
            __nv_bfloat16 chi = __float2bfloat16(Cn);
            __nv_bfloat16 clo = __float2bfloat16(Cn - __bfloat162float(chi));
            Astg[eoff]       = chi;     // s=0 plane
            Astg[eoff + 256] = clo;     // s=1 plane
        }
        __syncthreads();

        // ---- coalesced A-frag writeback: 2KB region for ksteps {2cb, 2cb+1} ----
        if (tid < 128) {
            uint4* dst = (uint4*)(d_Afrag[p1] + (size_t)rb * 16384 + cb * 1024);
            __stcg(dst + tid, ((const uint4*)Astg)[tid]);
        }
        __syncthreads();

        // ---- row-group barrier (16 blocks share this counter) ----
        if (tid == 0) {
            __threadfence();
            atomicAdd(barp, 1u);
            unsigned target = (unsigned)(t + 1) * 16u;
            while (*((volatile unsigned int*)barp) < target) { __nanosleep(20); }
            __threadfence();
        }
        __syncthreads();
    }
}

// ---------------- final: o gate + h = tanh(C_T)*o ----------------
__global__ void k_final_h(const int* __restrict__ xIdx, const float* __restrict__ Woc) {
    __shared__ float cps[Hn];
    int b = blockIdx.x;
    int tid = threadIdx.x;                         // 128
    const float* CTprev = d_CT[(Tn - 1) & 1];      // C_{T-1}, [h][b]
    const float* CTlast = d_CT[Tn & 1];            // C_T
    for (int k = tid; k < Hn; k += 128) cps[k] = CTprev[k * Bn + b];
    __syncthreads();
    int tok = xIdx[b * Tn + (Tn - 1)];
    float acc[4] = {0.f, 0.f, 0.f, 0.f};
    #pragma unroll 4
    for (int k = 0; k < Hn; k++) {
        float c = cps[k];
        const float* wr = Woc + k * Hn + tid;
        acc[0] = fmaf(c, wr[0],   acc[0]);
        acc[1] = fmaf(c, wr[128], acc[1]);
        acc[2] = fmaf(c, wr[256], acc[2]);
        acc[3] = fmaf(c, wr[384], acc[3]);
    }
    #pragma unroll
    for (int m = 0; m < 4; m++) {
        int h = tid + m * 128;
        float o = sigf(d_gtab[tok * 2048 + 1024 + h] + acc[m]);
        d_Hf[b * Hn + h] = tanhf(CTlast[h * Bn + b]) * o;
    }
}

// ---------------- final: logits + log_softmax ----------------
__global__ void k_final_p(const float* __restrict__ Wph, const float* __restrict__ bp,
                          float* __restrict__ out) {
    __shared__ float hs[Hn];
    __shared__ float red[128];
    int b = blockIdx.x;
    int tid = threadIdx.x;                         // 128
    for (int k = tid; k < Hn; k += 128) hs[k] = d_Hf[b * Hn + k];
    __syncthreads();
    float p = -INFINITY;
    if (tid < NCn) {
        p = bp[tid];
        #pragma unroll 4
        for (int k = 0; k < Hn; k++) p = fmaf(hs[k], Wph[k * NCn + tid], p);
    }
    red[tid] = p;
    __syncthreads();
    for (int s = 64; s > 0; s >>= 1) {
        if (tid < s) red[tid] = fmaxf(red[tid], red[tid + s]);
        __syncthreads();
    }
    float mx = red[0];
    __syncthreads();
    red[tid] = (tid < NCn) ? expf(p - mx) : 0.0f;
    __syncthreads();
    for (int s = 64; s > 0; s >>= 1) {
        if (tid < s) red[tid] += red[tid + s];
        __syncthreads();
    }
    float lse = mx + logf(red[0]);
    if (tid < NCn) out[b * NCn + tid] = p - lse;
}

// ---------------- launch ----------------
extern "C" void kernel_launch(void* const* d_in, const int* in_sizes, int n_in,
                              void* d_out, int out_size) {
    (void)in_sizes; (void)n_in; (void)out_size;
    const int*   x   = (const int*)  d_in[0];
    const float* emb = (const float*)d_in[1];
    const float* Wfx = (const float*)d_in[2];
    const float* Wfc = (const float*)d_in[3];
    const float* bf  = (const float*)d_in[4];
    const float* Wix = (const float*)d_in[5];
    const float* Wic = (const float*)d_in[6];
    const float* bi  = (const float*)d_in[7];
    const float* Wox = (const float*)d_in[8];
    const float* Woc = (const float*)d_in[9];
    const float* bo  = (const float*)d_in[10];
    const float* Wcx = (const float*)d_in[11];
    const float* bc  = (const float*)d_in[12];
    const float* Wph = (const float*)d_in[13];
    const float* bp  = (const float*)d_in[14];
    float* out = (float*)d_out;

    cudaFuncSetAttribute(k_recur, cudaFuncAttributeMaxDynamicSharedMemorySize, SMEM_R_BYTES);

    k_init<<<(131072 + 255) / 256, 256>>>();
    k_gtab<<<Vn, 256>>>(emb, Wfx, bf, Wix, bi, Wox, bo, Wcx, bc);
    k_wsplit<<<(16 * 32 * 8 * 2 * 32 + 255) / 256, 256>>>(Wfc, Wic);
    k_recur<<<GRID_R, THR_R, SMEM_R_BYTES>>>(x);
    k_final_h<<<Bn, 128>>>(x, Woc);
    k_final_p<<<Bn, 128>>>(Wph, bp, out);
}

// round 17
// speedup vs baseline: 5.7435x; 1.1181x over previous
#include <cuda_runtime.h>
#include <cuda_bf16.h>
#include <cstdint>

// Problem constants
#define Bn  128
#define Tn  512
#define In  128
#define Hn  512
#define NCn 100
#define Vn  101

// k_recur: 128 blocks = 8 row-tiles (16 batches) x 16 col-tiles (32 h-units)
#define GRID_R 128
#define THR_R  512        // 16 warps = (8 kslices) x (2 n-halves)

// smem layout (bytes): no B tile anymore (weight-stationary registers)
#define PS_ROW    34                      // padded floats per row (32 cols used)
#define PS_FLOATS (16 * 16 * PS_ROW)      // 16 slots x 16 rows x 34  (34816 B)
#define ASTG_OFF  (PS_FLOATS * 4)
#define SMEM_R_BYTES (ASTG_OFF + 2048)    // + 2KB A-frag writeback staging

typedef unsigned long long ull;

#define ADD2(accv, bv) \
    asm("add.rn.f32x2 %0, %0, %1;" : "+l"(accv) : "l"(bv))

// ---------------- device-global scratch ----------------
__device__ float          d_gtab[Vn * 4 * Hn];     // [tok][f,i,o,sig(c)][h]
__device__ ull            d_Bfrag[16 * 32 * 8 * 2 * 32];          // W frags (2MB)
__device__ __nv_bfloat16  d_Afrag[2][8 * 32 * 2 * 32 * 8];        // C frags, dbl-buffered
__device__ float          d_CT[2][Hn * Bn];        // fp32 cell state [h][b]
__device__ float          d_Hf[Bn * Hn];
__device__ unsigned int   d_barArr[8 * 32];

__device__ __forceinline__ float sigf(float x) { return 1.0f / (1.0f + expf(-x)); }

__device__ __forceinline__ void mma_bf16(float* d, const uint4 a, const ull b) {
    unsigned b0 = (unsigned)(b & 0xffffffffull);
    unsigned b1 = (unsigned)(b >> 32);
    asm volatile(
        "mma.sync.aligned.m16n8k16.row.col.f32.bf16.bf16.f32 "
        "{%0,%1,%2,%3}, {%4,%5,%6,%7}, {%8,%9}, {%0,%1,%2,%3};"
        : "+f"(d[0]), "+f"(d[1]), "+f"(d[2]), "+f"(d[3])
        : "r"(a.x), "r"(a.y), "r"(a.z), "r"(a.w), "r"(b0), "r"(b1));
}

// ---------------- init: zero C0 state, A frags (parity 0), barriers ----------------
__global__ void k_init() {
    int i = blockIdx.x * blockDim.x + threadIdx.x;
    if (i < Bn * Hn) d_CT[0][i] = 0.0f;
    if (i < 65536) ((unsigned*)d_Afrag)[i] = 0u;   // 131072 bf16 zeros = parity 0
    if (i < 8 * 32) d_barArr[i] = 0u;
}

// ---------------- token gate table ----------------
__global__ void k_gtab(const float* __restrict__ emb,
                       const float* __restrict__ Wfx, const float* __restrict__ bf,
                       const float* __restrict__ Wix, const float* __restrict__ bi,
                       const float* __restrict__ Wox, const float* __restrict__ bo,
                       const float* __restrict__ Wcx, const float* __restrict__ bc) {
    __shared__ float es[In];
    int v = blockIdx.x;
    int tid = threadIdx.x;                // 256
    if (tid < In) es[tid] = emb[v * In + tid];
    __syncthreads();
    for (int h = tid; h < Hn; h += 256) {
        float af = bf[h], ai = bi[h], ao = bo[h], ac = bc[h];
        #pragma unroll 4
        for (int k = 0; k < In; k++) {
            float e = es[k];
            af = fmaf(e, Wfx[k * Hn + h], af);
            ai = fmaf(e, Wix[k * Hn + h], ai);
            ao = fmaf(e, Wox[k * Hn + h], ao);
            ac = fmaf(e, Wcx[k * Hn + h], ac);
        }
        d_gtab[v * 2048 + h]        = af;
        d_gtab[v * 2048 + 512 + h]  = ai;
        d_gtab[v * 2048 + 1024 + h] = ao;
        d_gtab[v * 2048 + 1536 + h] = sigf(ac);   // c_tilde pre-sigmoid
    }
}

// ---------------- W hi/lo split -> mma B fragments ----------------
// d_Bfrag[cb][kstep][nt][s][lane]; packed col n = 2h + gate (0:f, 1:i)
__global__ void k_wsplit(const float* __restrict__ Wfc, const float* __restrict__ Wic) {
    int gid = blockIdx.x * blockDim.x + threadIdx.x;   // 262144
    if (gid >= 16 * 32 * 8 * 2 * 32) return;
    int lane  = gid & 31;
    int s     = (gid >> 5) & 1;
    int nt    = (gid >> 6) & 7;
    int kstep = (gid >> 9) & 31;
    int cb    = gid >> 14;
    int g  = lane >> 2;
    int tg = lane & 3;
    int n  = cb * 64 + nt * 8 + g;
    int h  = n >> 1;
    const float* Wsrc = (n & 1) ? Wic : Wfc;
    int k0 = kstep * 16 + 2 * tg;
    unsigned words[2];
    #pragma unroll
    for (int half8 = 0; half8 < 2; half8++) {
        float v0 = Wsrc[(k0 + half8 * 8) * Hn + h];
        float v1 = Wsrc[(k0 + half8 * 8 + 1) * Hn + h];
        __nv_bfloat16 e0, e1;
        if (s == 0) { e0 = __float2bfloat16(v0); e1 = __float2bfloat16(v1); }
        else {
            __nv_bfloat16 h0 = __float2bfloat16(v0), h1 = __float2bfloat16(v1);
            e0 = __float2bfloat16(v0 - __bfloat162float(h0));
            e1 = __float2bfloat16(v1 - __bfloat162float(h1));
        }
        unsigned w = ((unsigned)*(unsigned short*)&e1 << 16) | (unsigned)*(unsigned short*)&e0;
        words[half8] = w;
    }
    d_Bfrag[gid] = ((ull)words[1] << 32) | (ull)words[0];
}

// ---------------- persistent recurrent kernel (tensor-core mma, W in regs) ----------------
__global__ void __launch_bounds__(THR_R, 1) k_recur(const int* __restrict__ xIdx) {
    extern __shared__ char smraw[];
    float* Ps   = (float*)smraw;                     // [16 slot][16 r][34]
    __nv_bfloat16* Astg = (__nv_bfloat16*)(smraw + ASTG_OFF);  // [2 lk][2 s][256]

    const int tid = threadIdx.x;
    const int bx  = blockIdx.x;
    const int rb  = bx >> 4;              // 0..7  row tile (16 batches)
    const int cb  = bx & 15;              // 0..15 col tile (32 h-units)
    const int b0  = rb * 16;
    const int u0  = cb * 32;

    const int wid  = tid >> 5;            // 0..15
    const int lane = tid & 31;
    const int g    = lane >> 2;
    const int tg   = lane & 3;
    const int ks8  = wid >> 1;            // 0..7   4-kstep slice
    const int nh   = wid & 1;             // 0..1   n-half (4 nt)
    const int k0   = ks8 * 4;

    // ---- weight-stationary B fragments: 32 ull registers per lane ----
    ull B2[32];                           // [(kq*4 + ntl)*2 + s]
    {
        const ull* src = d_Bfrag + (size_t)cb * 16384;
        #pragma unroll
        for (int kq = 0; kq < 4; kq++)
            #pragma unroll
            for (int ntl = 0; ntl < 4; ntl++) {
                const ull* bb = src + (size_t)(k0 + kq) * 512 + (4 * nh + ntl) * 64 + lane;
                B2[(kq * 4 + ntl) * 2]     = bb[0];
                B2[(kq * 4 + ntl) * 2 + 1] = bb[32];
            }
    }

    // epilogue: one (row er, h-unit eu) per thread
    const int er   = tid & 15;            // 0..15
    const int eu   = tid >> 4;            // 0..31
    const int eb   = b0 + er;
    const int nh_e = eu >> 4;             // which n-half my column lives in
    // A-fragment staging coordinates for (er, h=u0+eu)
    const int ec     = eu & 15;
    const int elane  = (er & 7) * 4 + ((ec & 7) >> 1);
    const int ereg   = (er >> 3) + (((ec >> 3) & 1) << 1);
    const int ehalf  = ec & 1;
    const int eoff   = (nh_e * 2) * 256 + elane * 8 + ereg * 2 + ehalf;  // s=0 plane

    unsigned int* barp = &d_barArr[rb * 32];

    #pragma unroll 1
    for (int t = 0; t < Tn; t++) {
        const int p  = t & 1;
        const int p1 = (t + 1) & 1;

        // ---- minimal prefetch: token + fp32 C state ----
        int   tok  = xIdx[eb * Tn + t];
        float Cold = __ldcg(&d_CT[p][(u0 + eu) * Bn + eb]);

        // ---- direct-LDG A fragments for this warp's 4 ksteps (coalesced) ----
        const uint4* Afp = (const uint4*)(d_Afrag[p] + (size_t)rb * 16384);
        uint4 ah[4], al[4];
        #pragma unroll
        for (int kq = 0; kq < 4; kq++) {
            ah[kq] = __ldcg(Afp + ((k0 + kq) * 2 + 0) * 32 + lane);
            al[kq] = __ldcg(Afp + ((k0 + kq) * 2 + 1) * 32 + lane);
        }

        // ---- GEMM: 4 ksteps x 4 nt x 3 terms, B operands in registers ----
        float acc[4][4];
        #pragma unroll
        for (int ntl = 0; ntl < 4; ntl++)
            #pragma unroll
            for (int q = 0; q < 4; q++) acc[ntl][q] = 0.0f;

        #pragma unroll
        for (int kq = 0; kq < 4; kq++) {
            #pragma unroll
            for (int ntl = 0; ntl < 4; ntl++) {
                ull bh = B2[(kq * 4 + ntl) * 2];
                ull bl = B2[(kq * 4 + ntl) * 2 + 1];
                mma_bf16(acc[ntl], ah[kq], bh);   // Ch * Wh
                mma_bf16(acc[ntl], al[kq], bh);   // Cl * Wh
                mma_bf16(acc[ntl], ah[kq], bl);   // Ch * Wl
            }
        }

        // ---- gate-table loads (latency hides under partial store + sync) ----
        float gf0 = d_gtab[tok * 2048 + u0 + eu];
        float gi0 = d_gtab[tok * 2048 + 512 + u0 + eu];
        float ct0 = d_gtab[tok * 2048 + 1536 + u0 + eu];

        // ---- store per-warp partials: rows {g, g+8}, local cols ntl*8+2tg ----
        {
            float* base = Ps + wid * (16 * PS_ROW);
            #pragma unroll
            for (int ntl = 0; ntl < 4; ntl++) {
                *(float2*)(base + g * PS_ROW + ntl * 8 + 2 * tg)       =
                    make_float2(acc[ntl][0], acc[ntl][1]);
                *(float2*)(base + (g + 8) * PS_ROW + ntl * 8 + 2 * tg) =
                    make_float2(acc[ntl][2], acc[ntl][3]);
            }
        }
        __syncthreads();

        // ---- reduce 8 matching slots + gate epilogue + state stores ----
        {
            const ull* pp = (const ull*)Ps + nh_e * 272 + er * 17 + (eu & 15);
            ull s0 = 0ull, s1 = 0ull, s2 = 0ull, s3 = 0ull;
            #pragma unroll
            for (int j = 0; j < 8; j += 4) {
                ull v0 = pp[(j + 0) * 544];
                ull v1 = pp[(j + 1) * 544];
                ull v2 = pp[(j + 2) * 544];
                ull v3 = pp[(j + 3) * 544];
                ADD2(s0, v0); ADD2(s1, v1); ADD2(s2, v2); ADD2(s3, v3);
            }
            ADD2(s0, s1); ADD2(s2, s3); ADD2(s0, s2);
            float sf = __uint_as_float((unsigned)(s0 & 0xffffffffu));
            float si = __uint_as_float((unsigned)(s0 >> 32));
            float f  = sigf(gf0 + sf);
            float ig = sigf(gi0 + si);
            float Cn = (tok > 0) ? fmaf(Cold, f, ct0 * ig) : 0.0f;
            // fp32 state (exact carry)
            __stcg(&d_CT[p1][(u0 + eu) * Bn + eb], Cn);
            // hi/lo bf16 into smem staging (fragment order)
            __nv_bfloat16 chi = __float2bfloat16(Cn);
            __nv_bfloat16 clo = __float2bfloat16(Cn - __bfloat162float(chi));
            Astg[eoff]       = chi;     // s=0 plane
            Astg[eoff + 256] = clo;     // s=1 plane
        }
        __syncthreads();

        // ---- coalesced A-frag writeback: 2KB region for ksteps {2cb, 2cb+1} ----
        if (tid < 128) {
            uint4* dst = (uint4*)(d_Afrag[p1] + (size_t)rb * 16384 + cb * 1024);
            __stcg(dst + tid, ((const uint4*)Astg)[tid]);
        }
        __syncthreads();

        // ---- row-group barrier (16 blocks share this counter) ----
        if (tid == 0) {
            __threadfence();
            atomicAdd(barp, 1u);
            unsigned target = (unsigned)(t + 1) * 16u;
            while (*((volatile unsigned int*)barp) < target) { __nanosleep(20); }
            __threadfence();
        }
        __syncthreads();
    }
}

// ---------------- final: o gate + h = tanh(C_T)*o ----------------
__global__ void k_final_h(const int* __restrict__ xIdx, const float* __restrict__ Woc) {
    __shared__ float cps[Hn];
    int b = blockIdx.x;
    int tid = threadIdx.x;                         // 128
    const float* CTprev = d_CT[(Tn - 1) & 1];      // C_{T-1}, [h][b]
    const float* CTlast = d_CT[Tn & 1];            // C_T
    for (int k = tid; k < Hn; k += 128) cps[k] = CTprev[k * Bn + b];
    __syncthreads();
    int tok = xIdx[b * Tn + (Tn - 1)];
    float acc[4] = {0.f, 0.f, 0.f, 0.f};
    #pragma unroll 4
    for (int k = 0; k < Hn; k++) {
        float c = cps[k];
        const float* wr = Woc + k * Hn + tid;
        acc[0] = fmaf(c, wr[0],   acc[0]);
        acc[1] = fmaf(c, wr[128], acc[1]);
        acc[2] = fmaf(c, wr[256], acc[2]);
        acc[3] = fmaf(c, wr[384], acc[3]);
    }
    #pragma unroll
    for (int m = 0; m < 4; m++) {
        int h = tid + m * 128;
        float o = sigf(d_gtab[tok * 2048 + 1024 + h] + acc[m]);
        d_Hf[b * Hn + h] = tanhf(CTlast[h * Bn + b]) * o;
    }
}

// ---------------- final: logits + log_softmax ----------------
__global__ void k_final_p(const float* __restrict__ Wph, const float* __restrict__ bp,
                          float* __restrict__ out) {
    __shared__ float hs[Hn];
    __shared__ float red[128];
    int b = blockIdx.x;
    int tid = threadIdx.x;                         // 128
    for (int k = tid; k < Hn; k += 128) hs[k] = d_Hf[b * Hn + k];
    __syncthreads();
    float p = -INFINITY;
    if (tid < NCn) {
        p = bp[tid];
        #pragma unroll 4
        for (int k = 0; k < Hn; k++) p = fmaf(hs[k], Wph[k * NCn + tid], p);
    }
    red[tid] = p;
    __syncthreads();
    for (int s = 64; s > 0; s >>= 1) {
        if (tid < s) red[tid] = fmaxf(red[tid], red[tid + s]);
        __syncthreads();
    }
    float mx = red[0];
    __syncthreads();
    red[tid] = (tid < NCn) ? expf(p - mx) : 0.0f;
    __syncthreads();
    for (int s = 64; s > 0; s >>= 1) {
        if (tid < s) red[tid] += red[tid + s];
        __syncthreads();
    }
    float lse = mx + logf(red[0]);
    if (tid < NCn) out[b * NCn + tid] = p - lse;
}

// ---------------- launch ----------------
extern "C" void kernel_launch(void* const* d_in, const int* in_sizes, int n_in,
                              void* d_out, int out_size) {
    (void)in_sizes; (void)n_in; (void)out_size;
    const int*   x   = (const int*)  d_in[0];
    const float* emb = (const float*)d_in[1];
    const float* Wfx = (const float*)d_in[2];
    const float* Wfc = (const float*)d_in[3];
    const float* bf  = (const float*)d_in[4];
    const float* Wix = (const float*)d_in[5];
    const float* Wic = (const float*)d_in[6];
    const float* bi  = (const float*)d_in[7];
    const float* Wox = (const float*)d_in[8];
    const float* Woc = (const float*)d_in[9];
    const float* bo  = (const float*)d_in[10];
    const float* Wcx = (const float*)d_in[11];
    const float* bc  = (const float*)d_in[12];
    const float* Wph = (const float*)d_in[13];
    const float* bp  = (const float*)d_in[14];
    float* out = (float*)d_out;

    cudaFuncSetAttribute(k_recur, cudaFuncAttributeMaxDynamicSharedMemorySize, SMEM_R_BYTES);

    k_init<<<(131072 + 255) / 256, 256>>>();
    k_gtab<<<Vn, 256>>>(emb, Wfx, bf, Wix, bi, Wox, bo, Wcx, bc);
    k_wsplit<<<(16 * 32 * 8 * 2 * 32 + 255) / 256, 256>>>(Wfc, Wic);
    k_recur<<<GRID_R, THR_R, SMEM_R_BYTES>>>(x);
    k_final_h<<<Bn, 128>>>(x, Woc);
    k_final_p<<<Bn, 128>>>(Wph, bp, out);
}